// round 16
// baseline (speedup 1.0000x reference)
#include <cuda_runtime.h>
#include <cuda_fp16.h>
#include <mma.h>
#include <math.h>
#include <cstdint>

using namespace nvcuda;

#define NN 100000
#define EE 1000000
#define RR 3
#define IN_DIM 128
#define OUT_DIM 64

static constexpr int N3 = RR * NN;
static constexpr int E3 = RR * EE;
static constexpr int NB_SCAN = (N3 + 255) / 256;   // 1172
static constexpr int HB = (E3 + 255) / 256;        // 11719 edge-parallel blocks
static constexpr int CB = (NN * (IN_DIM / 4) + 255) / 256;  // convert blocks
static constexpr int GB = (NN + 255) / 256;        // 391 gemm row-tiles

// ---------------- scratch (BSS zero; re-zeroed by agg2 tail each run) --------
__device__ int     g_cnt[N3];
__device__ int     g_rowptr[N3 + 1];
__device__ int     g_col[E3];
__device__ unsigned long long g_lookback[NB_SCAN];
__device__ __half2 g_h2[(size_t)N3 * (OUT_DIM / 2)];
__device__ float   g_alsrc[N3];
__device__ float   g_aldst[N3];
__device__ __half2 g_xh[(size_t)NN * (IN_DIM / 2)];
__device__ __half2 g_hmid[(size_t)NN * (OUT_DIM / 2)];

// ---------------- cp.async helpers -------------------------------------------
__device__ __forceinline__ void cp_async16(uint32_t dst_smem, const void* src, int src_bytes) {
    asm volatile("cp.async.ca.shared.global [%0], [%1], 16, %2;\n"
                 :: "r"(dst_smem), "l"(src), "r"(src_bytes));
}
__device__ __forceinline__ void cp_commit() {
    asm volatile("cp.async.commit_group;\n");
}
template <int N>
__device__ __forceinline__ void cp_wait() {
    asm volatile("cp.async.wait_group %0;\n" :: "n"(N));
}

// ---------------- fused hist + x->fp16 convert -------------------------------
__global__ void k_hist_convert(const int* __restrict__ e0, const int* __restrict__ e1,
                               const int* __restrict__ e2, const float4* __restrict__ x) {
    int b = blockIdx.x;
    if (b < HB) {
        int i = b * 256 + threadIdx.x;
        if (i >= E3) return;
        int r = i / EE, e = i - r * EE;
        const int* ei = (r == 0) ? e0 : (r == 1) ? e1 : e2;
        int dst = ei[EE + e];
        atomicAdd(&g_cnt[r * NN + dst], 1);
    } else {
        int i = (b - HB) * 256 + threadIdx.x;
        if (i >= NN * (IN_DIM / 4)) return;
        float4 v = x[i];
        g_xh[i * 2]     = __float22half2_rn(make_float2(v.x, v.y));
        g_xh[i * 2 + 1] = __float22half2_rn(make_float2(v.z, v.w));
    }
}

__global__ void k_scan_lookback() {
    __shared__ int sh[256];
    __shared__ int s_prefix;
    int b = blockIdx.x, tid = threadIdx.x;
    int i = b * 256 + tid;
    int v = (i < N3) ? g_cnt[i] : 0;
    sh[tid] = v;
    __syncthreads();
    for (int o = 1; o < 256; o <<= 1) {
        int add = (tid >= o) ? sh[tid - o] : 0;
        __syncthreads();
        sh[tid] += add;
        __syncthreads();
    }
    int total = sh[255];
    if (tid == 0) {
        if (b == 0) {
            *(volatile unsigned long long*)&g_lookback[0] =
                (2ULL << 32) | (unsigned)total;
            s_prefix = 0;
        } else {
            *(volatile unsigned long long*)&g_lookback[b] =
                (1ULL << 32) | (unsigned)total;
            int run = 0, p = b - 1;
            while (true) {
                unsigned long long st = *(volatile unsigned long long*)&g_lookback[p];
                unsigned stt = (unsigned)(st >> 32);
                if (stt == 2u) { run += (int)(st & 0xffffffffu); break; }
                else if (stt == 1u) { run += (int)(st & 0xffffffffu); p--; }
                else { __nanosleep(20); }
            }
            *(volatile unsigned long long*)&g_lookback[b] =
                (2ULL << 32) | (unsigned)(run + total);
            s_prefix = run;
        }
    }
    __syncthreads();
    int excl = s_prefix + sh[tid] - v;
    if (i < N3) { g_rowptr[i] = excl; g_cnt[i] = excl; }
    if (i == 0) g_rowptr[N3] = E3;
}

// ---------------- shared GEMM body (fp16 wmma, cp.async double buffer) -------
template <int K>
__device__ __forceinline__ void gemm_body(
        int gx, int r,
        const __half* __restrict__ X, const float* __restrict__ W,
        const float* __restrict__ asrc, const float* __restrict__ adst) {
    constexpr int XLDH = 24;
    constexpr int WLDH = 72;
    constexpr int OLD  = 68;
    constexpr int W_BYTES = K * WLDH * 2;
    constexpr int XCH_BYTES = 256 * XLDH * 2;
    constexpr int MAIN_BYTES = W_BYTES + 2 * XCH_BYTES;
    constexpr int O_BYTES = 128 * OLD * 4;
    constexpr int BUF_BYTES = (MAIN_BYTES > O_BYTES) ? MAIN_BYTES : O_BYTES;
    constexpr int NSTEP = K / 16;
    __shared__ __align__(16) char buf[BUF_BYTES];
    __half* sW = (__half*)buf;
    __half* sX = (__half*)(buf + W_BYTES);
    float*  sO = (float*)buf;

    const int row0 = gx * 256;
    const int t = threadIdx.x;
    const int w = t >> 5;
    const uint32_t sx_base = (uint32_t)__cvta_generic_to_shared(sX);

    {
        const float4* Wr4 = (const float4*)(W + (size_t)r * K * OUT_DIM);
        for (int i = t; i < K * 16; i += 256) {
            float4 v = Wr4[i];
            int row = i >> 4, c4 = (i & 15) * 4;
            __half2* dstp = (__half2*)&sW[row * WLDH + c4];
            dstp[0] = __float22half2_rn(make_float2(v.x, v.y));
            dstp[1] = __float22half2_rn(make_float2(v.z, v.w));
        }
    }

    auto stage = [&](int bi, int kk) {
#pragma unroll
        for (int p = 0; p < 2; p++) {
            int i = t + p * 256;
            int row = i >> 1, h16 = i & 1;
            int grow = row0 + row;
            uint32_t dst = sx_base + bi * XCH_BYTES + (row * XLDH + h16 * 8) * 2;
            const void* src = X + (size_t)grow * K + kk + h16 * 8;
            cp_async16(dst, src, grow < NN ? 16 : 0);
        }
        cp_commit();
    };

    wmma::fragment<wmma::accumulator, 16, 16, 16, float> acc[2][4];
#pragma unroll
    for (int mi = 0; mi < 2; mi++)
#pragma unroll
        for (int ct = 0; ct < 4; ct++) wmma::fill_fragment(acc[mi][ct], 0.f);

    stage(0, 0);
#pragma unroll
    for (int s = 0; s < NSTEP; s++) {
        if (s + 1 < NSTEP) stage((s + 1) & 1, (s + 1) * 16);
        if (s + 1 < NSTEP) cp_wait<1>(); else cp_wait<0>();
        __syncthreads();
        const __half* sXc = sX + (s & 1) * (XCH_BYTES / 2);
        wmma::fragment<wmma::matrix_a, 16, 16, 16, __half, wmma::row_major> af[2];
#pragma unroll
        for (int mi = 0; mi < 2; mi++)
            wmma::load_matrix_sync(af[mi], &sXc[(w * 32 + mi * 16) * XLDH], XLDH);
#pragma unroll
        for (int ct = 0; ct < 4; ct++) {
            wmma::fragment<wmma::matrix_b, 16, 16, 16, __half, wmma::row_major> bf;
            wmma::load_matrix_sync(bf, &sW[s * 16 * WLDH + ct * 16], WLDH);
#pragma unroll
            for (int mi = 0; mi < 2; mi++)
                wmma::mma_sync(acc[mi][ct], af[mi], bf, acc[mi][ct]);
        }
        __syncthreads();
    }

#pragma unroll
    for (int ph = 0; ph < 2; ph++) {
        if ((w >> 2) == ph) {
#pragma unroll
            for (int mi = 0; mi < 2; mi++)
#pragma unroll
                for (int ct = 0; ct < 4; ct++)
                    wmma::store_matrix_sync(
                        &sO[(w * 32 + mi * 16 - ph * 128) * OLD + ct * 16],
                        acc[mi][ct], OLD, wmma::mem_row_major);
        }
        __syncthreads();
        {
            int row = t >> 1, half = t & 1;
            int grow = row0 + ph * 128 + row;
            float s = 0.f, d = 0.f;
            __half2 hv[16];
            const float* orow = &sO[row * OLD + half * 32];
            const float* av = asrc + r * OUT_DIM + half * 32;
            const float* dv = adst + r * OUT_DIM + half * 32;
#pragma unroll
            for (int j = 0; j < 16; j++) {
                float v0 = orow[2 * j], v1 = orow[2 * j + 1];
                hv[j] = __float22half2_rn(make_float2(v0, v1));
                s = fmaf(v0, __ldg(&av[2 * j]), s);
                s = fmaf(v1, __ldg(&av[2 * j + 1]), s);
                d = fmaf(v0, __ldg(&dv[2 * j]), d);
                d = fmaf(v1, __ldg(&dv[2 * j + 1]), d);
            }
            s += __shfl_xor_sync(0xffffffffu, s, 1);
            d += __shfl_xor_sync(0xffffffffu, d, 1);
            if (grow < NN) {
                float4* dstp = (float4*)(g_h2 + (size_t)(r * NN + grow) * 32 + half * 16);
                const float4* srcp = (const float4*)hv;
#pragma unroll
                for (int q = 0; q < 4; q++) dstp[q] = srcp[q];
                if (half == 0) {
                    g_alsrc[r * NN + grow] = s;
                    g_aldst[r * NN + grow] = d;
                }
            }
        }
        __syncthreads();
    }
}

// ---------------- fat kernel: scatter blocks + gemm1 blocks ------------------
__global__ __launch_bounds__(256) void k_scatter_gemm1(
        const int* __restrict__ e0, const int* __restrict__ e1,
        const int* __restrict__ e2,
        const __half* __restrict__ X, const float* __restrict__ W,
        const float* __restrict__ asrc, const float* __restrict__ adst) {
    int b = blockIdx.x;
    if (b < HB) {
        int i = b * 256 + threadIdx.x;
        if (i >= E3) return;
        int r = i / EE, e = i - r * EE;
        const int* ei = (r == 0) ? e0 : (r == 1) ? e1 : e2;
        int src = ei[e];
        int dst = ei[EE + e];
        int pos = atomicAdd(&g_cnt[r * NN + dst], 1);
        g_col[pos] = src;
    } else {
        int q = b - HB;
        gemm_body<IN_DIM>(q % GB, q / GB, X, W, asrc, adst);
    }
}

__global__ __launch_bounds__(256) void k_gemm2(
        const __half* __restrict__ X, const float* __restrict__ W,
        const float* __restrict__ asrc, const float* __restrict__ adst) {
    gemm_body<OUT_DIM>(blockIdx.x, blockIdx.z, X, W, asrc, adst);
}

// ---------------- aggregation (serial; LAYER2 re-zeroes CSR scratch) ---------
template <int LAYER>
__global__ void k_agg(const float* __restrict__ bias, void* __restrict__ outp) {
    int gid = blockIdx.x * blockDim.x + threadIdx.x;
    if (LAYER == 2) {
        if (gid < N3) g_cnt[gid] = 0;
        if (gid < NB_SCAN) g_lookback[gid] = 0ULL;
    }
    int d = gid >> 5;
    int lane = gid & 31;
    if (d >= NN) return;
    float t0 = 0.f, t1 = 0.f;
#pragma unroll
    for (int r = 0; r < RR; r++) {
        int idx = r * NN + d;
        int s = g_rowptr[idx], e = g_rowptr[idx + 1];
        float ad = g_aldst[idx];
        float acc0 = 0.f, acc1 = 0.f, den = 0.f;
        const __half2* hbase = g_h2 + (size_t)r * NN * (OUT_DIM / 2);
        const float* albase = g_alsrc + r * NN;
        for (int j = s; j < e; j++) {
            int src = g_col[j];
            float al = albase[src] + ad;
            float lr = al > 0.f ? al : 0.2f * al;
            float w = __expf(lr);
            den += w;
            float2 hv = __half22float2(hbase[(size_t)src * (OUT_DIM / 2) + lane]);
            acc0 = fmaf(w, hv.x, acc0);
            acc1 = fmaf(w, hv.y, acc1);
        }
        if (e > s) {
            float inv = 1.f / den;
            t0 = fmaf(acc0, inv, t0);
            t1 = fmaf(acc1, inv, t1);
        }
        t0 += __ldg(&bias[r * OUT_DIM + 2 * lane]);
        t1 += __ldg(&bias[r * OUT_DIM + 2 * lane + 1]);
    }
    t0 *= (1.f / 3.f);
    t1 *= (1.f / 3.f);
    if (LAYER == 1) {
        float sq = t0 * t0 + t1 * t1;
#pragma unroll
        for (int o = 16; o > 0; o >>= 1) sq += __shfl_xor_sync(0xffffffffu, sq, o);
        float inv = 1.f / fmaxf(sqrtf(sq), 1e-12f);
        t0 = fmaxf(t0 * inv, 0.f);
        t1 = fmaxf(t1 * inv, 0.f);
        ((__half2*)outp)[(size_t)d * (OUT_DIM / 2) + lane] =
            __float22half2_rn(make_float2(t0, t1));
    } else {
        ((float2*)outp)[(size_t)d * (OUT_DIM / 2) + lane] = make_float2(t0, t1);
    }
}

// ---------------- launch -----------------------------------------------------
extern "C" void kernel_launch(void* const* d_in, const int* in_sizes, int n_in,
                              void* d_out, int out_size) {
    const float* x      = (const float*)d_in[0];
    const int*   ei0    = (const int*)d_in[1];
    const int*   ei1    = (const int*)d_in[2];
    const int*   ei2    = (const int*)d_in[3];
    const float* W1     = (const float*)d_in[4];
    const float* asrc1  = (const float*)d_in[5];
    const float* adst1  = (const float*)d_in[6];
    const float* b1     = (const float*)d_in[7];
    const float* W2     = (const float*)d_in[8];
    const float* asrc2  = (const float*)d_in[9];
    const float* adst2  = (const float*)d_in[10];
    const float* b2     = (const float*)d_in[11];

    __half* xh;   cudaGetSymbolAddress((void**)&xh, g_xh);
    __half* hmid; cudaGetSymbolAddress((void**)&hmid, g_hmid);

    // g_cnt / g_lookback are zero on entry (BSS first run; agg2 tail thereafter)
    k_hist_convert<<<HB + CB, 256>>>(ei0, ei1, ei2, (const float4*)x);   // launch 1
    k_scan_lookback<<<NB_SCAN, 256>>>();                                  // launch 2
    k_scatter_gemm1<<<HB + GB * RR, 256>>>(ei0, ei1, ei2,
                                           xh, W1, asrc1, adst1);         // launch 3
    k_agg<1><<<(NN * 32 + 255) / 256, 256>>>(b1, hmid);                  // launch 4 (captured)

    dim3 ggrid(GB, 1, RR);
    k_gemm2<<<ggrid, 256>>>(hmid, W2, asrc2, adst2);                     // launch 5
    k_agg<2><<<(NN * 32 + 255) / 256, 256>>>(b2, d_out);                 // launch 6
}

// round 17
// speedup vs baseline: 1.0510x; 1.0510x over previous
#include <cuda_runtime.h>
#include <cuda_fp16.h>
#include <mma.h>
#include <math.h>
#include <cstdint>

using namespace nvcuda;

#define NN 100000
#define EE 1000000
#define RR 3
#define IN_DIM 128
#define OUT_DIM 64

static constexpr int N3 = RR * NN;
static constexpr int E3 = RR * EE;
static constexpr int NB_SCAN = (N3 + 255) / 256;   // 1172
static constexpr int HB = (E3 + 255) / 256;
static constexpr int CB = (NN * (IN_DIM / 4) + 255) / 256;
static constexpr int GB = (NN + 255) / 256;

// ---------------- scratch (BSS zero; re-zeroed by agg2 tail each run) --------
__device__ int     g_cnt[N3];
__device__ int     g_rowptr[N3 + 1];
__device__ int2    g_ew[E3];        // per CSR slot: {src*32, weight bits}
__device__ int     g_dstE[E3];      // dst per CSR slot (for weight kernel)
__device__ unsigned long long g_lookback[NB_SCAN];
__device__ __half2 g_h2[(size_t)N3 * (OUT_DIM / 2)];
__device__ float   g_alsrc[N3];
__device__ float   g_aldst[N3];
__device__ __half2 g_xh[(size_t)NN * (IN_DIM / 2)];
__device__ __half2 g_hmid[(size_t)NN * (OUT_DIM / 2)];

// ---------------- cp.async helpers -------------------------------------------
__device__ __forceinline__ void cp_async16(uint32_t dst_smem, const void* src, int src_bytes) {
    asm volatile("cp.async.ca.shared.global [%0], [%1], 16, %2;\n"
                 :: "r"(dst_smem), "l"(src), "r"(src_bytes));
}
__device__ __forceinline__ void cp_commit() {
    asm volatile("cp.async.commit_group;\n");
}
template <int N>
__device__ __forceinline__ void cp_wait() {
    asm volatile("cp.async.wait_group %0;\n" :: "n"(N));
}

// ---------------- fused hist + x->fp16 convert -------------------------------
__global__ void k_hist_convert(const int* __restrict__ e0, const int* __restrict__ e1,
                               const int* __restrict__ e2, const float4* __restrict__ x) {
    int b = blockIdx.x;
    if (b < HB) {
        int i = b * 256 + threadIdx.x;
        if (i >= E3) return;
        int r = i / EE, e = i - r * EE;
        const int* ei = (r == 0) ? e0 : (r == 1) ? e1 : e2;
        int dst = ei[EE + e];
        atomicAdd(&g_cnt[r * NN + dst], 1);
    } else {
        int i = (b - HB) * 256 + threadIdx.x;
        if (i >= NN * (IN_DIM / 4)) return;
        float4 v = x[i];
        g_xh[i * 2]     = __float22half2_rn(make_float2(v.x, v.y));
        g_xh[i * 2 + 1] = __float22half2_rn(make_float2(v.z, v.w));
    }
}

__global__ void k_scan_lookback() {
    __shared__ int sh[256];
    __shared__ int s_prefix;
    int b = blockIdx.x, tid = threadIdx.x;
    int i = b * 256 + tid;
    int v = (i < N3) ? g_cnt[i] : 0;
    sh[tid] = v;
    __syncthreads();
    for (int o = 1; o < 256; o <<= 1) {
        int add = (tid >= o) ? sh[tid - o] : 0;
        __syncthreads();
        sh[tid] += add;
        __syncthreads();
    }
    int total = sh[255];
    if (tid == 0) {
        if (b == 0) {
            *(volatile unsigned long long*)&g_lookback[0] =
                (2ULL << 32) | (unsigned)total;
            s_prefix = 0;
        } else {
            *(volatile unsigned long long*)&g_lookback[b] =
                (1ULL << 32) | (unsigned)total;
            int run = 0, p = b - 1;
            while (true) {
                unsigned long long st = *(volatile unsigned long long*)&g_lookback[p];
                unsigned stt = (unsigned)(st >> 32);
                if (stt == 2u) { run += (int)(st & 0xffffffffu); break; }
                else if (stt == 1u) { run += (int)(st & 0xffffffffu); p--; }
                else { __nanosleep(20); }
            }
            *(volatile unsigned long long*)&g_lookback[b] =
                (2ULL << 32) | (unsigned)(run + total);
            s_prefix = run;
        }
    }
    __syncthreads();
    int excl = s_prefix + sh[tid] - v;
    if (i < N3) { g_rowptr[i] = excl; g_cnt[i] = excl; }
    if (i == 0) g_rowptr[N3] = E3;
}

__global__ void k_scatter(const int* __restrict__ e0, const int* __restrict__ e1,
                          const int* __restrict__ e2) {
    int i = blockIdx.x * blockDim.x + threadIdx.x;
    if (i >= E3) return;
    int r = i / EE, e = i - r * EE;
    const int* ei = (r == 0) ? e0 : (r == 1) ? e1 : e2;
    int src = ei[e];
    int dst = ei[EE + e];
    int pos = atomicAdd(&g_cnt[r * NN + dst], 1);
    g_ew[pos].x = src << 5;        // src * 32 (half2 row offset)
    g_dstE[pos] = dst;
}

// ---------------- per-edge weight: w = exp(leaky(alsrc+aldst)) ---------------
__global__ void k_weight() {
    int i = blockIdx.x * blockDim.x + threadIdx.x;
    if (i >= E3) return;
    int r = i / EE;
    int src = g_ew[i].x >> 5;
    int dst = g_dstE[i];
    float al = __ldg(&g_alsrc[r * NN + src]) + __ldg(&g_aldst[r * NN + dst]);
    float lr = fmaxf(al, 0.2f * al);
    g_ew[i].y = __float_as_int(__expf(lr));
}

// ---------------- fp16 tensor-core GEMM: 256-row tile, cp.async 2-stage ------
template <int K>
__global__ __launch_bounds__(256) void k_gemm_tc(
        const __half* __restrict__ X, const float* __restrict__ W,
        const float* __restrict__ asrc, const float* __restrict__ adst) {
    constexpr int XLDH = 24;
    constexpr int WLDH = 72;
    constexpr int OLD  = 68;
    constexpr int W_BYTES = K * WLDH * 2;
    constexpr int XCH_BYTES = 256 * XLDH * 2;
    constexpr int MAIN_BYTES = W_BYTES + 2 * XCH_BYTES;
    constexpr int O_BYTES = 128 * OLD * 4;
    constexpr int BUF_BYTES = (MAIN_BYTES > O_BYTES) ? MAIN_BYTES : O_BYTES;
    constexpr int NSTEP = K / 16;
    __shared__ __align__(16) char buf[BUF_BYTES];
    __half* sW = (__half*)buf;
    __half* sX = (__half*)(buf + W_BYTES);
    float*  sO = (float*)buf;

    const int r = blockIdx.z;
    const int row0 = blockIdx.x * 256;
    const int t = threadIdx.x;
    const int w = t >> 5;
    const uint32_t sx_base = (uint32_t)__cvta_generic_to_shared(sX);

    {
        const float4* Wr4 = (const float4*)(W + (size_t)r * K * OUT_DIM);
        for (int i = t; i < K * 16; i += 256) {
            float4 v = Wr4[i];
            int row = i >> 4, c4 = (i & 15) * 4;
            __half2* dstp = (__half2*)&sW[row * WLDH + c4];
            dstp[0] = __float22half2_rn(make_float2(v.x, v.y));
            dstp[1] = __float22half2_rn(make_float2(v.z, v.w));
        }
    }

    auto stage = [&](int bi, int kk) {
#pragma unroll
        for (int p = 0; p < 2; p++) {
            int i = t + p * 256;
            int row = i >> 1, h16 = i & 1;
            int grow = row0 + row;
            uint32_t dst = sx_base + bi * XCH_BYTES + (row * XLDH + h16 * 8) * 2;
            const void* src = X + (size_t)grow * K + kk + h16 * 8;
            cp_async16(dst, src, grow < NN ? 16 : 0);
        }
        cp_commit();
    };

    wmma::fragment<wmma::accumulator, 16, 16, 16, float> acc[2][4];
#pragma unroll
    for (int mi = 0; mi < 2; mi++)
#pragma unroll
        for (int ct = 0; ct < 4; ct++) wmma::fill_fragment(acc[mi][ct], 0.f);

    stage(0, 0);
#pragma unroll
    for (int s = 0; s < NSTEP; s++) {
        if (s + 1 < NSTEP) stage((s + 1) & 1, (s + 1) * 16);
        if (s + 1 < NSTEP) cp_wait<1>(); else cp_wait<0>();
        __syncthreads();
        const __half* sXc = sX + (s & 1) * (XCH_BYTES / 2);
        wmma::fragment<wmma::matrix_a, 16, 16, 16, __half, wmma::row_major> af[2];
#pragma unroll
        for (int mi = 0; mi < 2; mi++)
            wmma::load_matrix_sync(af[mi], &sXc[(w * 32 + mi * 16) * XLDH], XLDH);
#pragma unroll
        for (int ct = 0; ct < 4; ct++) {
            wmma::fragment<wmma::matrix_b, 16, 16, 16, __half, wmma::row_major> bf;
            wmma::load_matrix_sync(bf, &sW[s * 16 * WLDH + ct * 16], WLDH);
#pragma unroll
            for (int mi = 0; mi < 2; mi++)
                wmma::mma_sync(acc[mi][ct], af[mi], bf, acc[mi][ct]);
        }
        __syncthreads();
    }

#pragma unroll
    for (int ph = 0; ph < 2; ph++) {
        if ((w >> 2) == ph) {
#pragma unroll
            for (int mi = 0; mi < 2; mi++)
#pragma unroll
                for (int ct = 0; ct < 4; ct++)
                    wmma::store_matrix_sync(
                        &sO[(w * 32 + mi * 16 - ph * 128) * OLD + ct * 16],
                        acc[mi][ct], OLD, wmma::mem_row_major);
        }
        __syncthreads();
        {
            int row = t >> 1, half = t & 1;
            int grow = row0 + ph * 128 + row;
            float s = 0.f, d = 0.f;
            __half2 hv[16];
            const float* orow = &sO[row * OLD + half * 32];
            const float* av = asrc + r * OUT_DIM + half * 32;
            const float* dv = adst + r * OUT_DIM + half * 32;
#pragma unroll
            for (int j = 0; j < 16; j++) {
                float v0 = orow[2 * j], v1 = orow[2 * j + 1];
                hv[j] = __float22half2_rn(make_float2(v0, v1));
                s = fmaf(v0, __ldg(&av[2 * j]), s);
                s = fmaf(v1, __ldg(&av[2 * j + 1]), s);
                d = fmaf(v0, __ldg(&dv[2 * j]), d);
                d = fmaf(v1, __ldg(&dv[2 * j + 1]), d);
            }
            s += __shfl_xor_sync(0xffffffffu, s, 1);
            d += __shfl_xor_sync(0xffffffffu, d, 1);
            if (grow < NN) {
                float4* dstp = (float4*)(g_h2 + (size_t)(r * NN + grow) * 32 + half * 16);
                const float4* srcp = (const float4*)hv;
#pragma unroll
                for (int q = 0; q < 4; q++) dstp[q] = srcp[q];
                if (half == 0) {
                    g_alsrc[r * NN + grow] = s;
                    g_aldst[r * NN + grow] = d;
                }
            }
        }
        __syncthreads();
    }
}

// ---------------- aggregation: lean inner loop over (src32, w) pairs ---------
template <int LAYER>
__global__ void k_agg(const float* __restrict__ bias, void* __restrict__ outp) {
    int gid = blockIdx.x * blockDim.x + threadIdx.x;
    if (LAYER == 2) {
        if (gid < N3) g_cnt[gid] = 0;
        if (gid < NB_SCAN) g_lookback[gid] = 0ULL;
    }
    int d = gid >> 5;
    int lane = gid & 31;
    if (d >= NN) return;
    float t0 = 0.f, t1 = 0.f;
#pragma unroll
    for (int r = 0; r < RR; r++) {
        int idx = r * NN + d;
        int s = g_rowptr[idx], e = g_rowptr[idx + 1];
        float acc0 = 0.f, acc1 = 0.f, den = 0.f;
        const __half2* hbase = g_h2 + (size_t)r * NN * (OUT_DIM / 2) + lane;
        for (int j = s; j < e; j++) {
            int2 p = __ldg(&g_ew[j]);
            float w = __int_as_float(p.y);
            den += w;
            float2 hv = __half22float2(hbase[p.x]);
            acc0 = fmaf(w, hv.x, acc0);
            acc1 = fmaf(w, hv.y, acc1);
        }
        if (e > s) {
            float inv = 1.f / den;
            t0 = fmaf(acc0, inv, t0);
            t1 = fmaf(acc1, inv, t1);
        }
        t0 += __ldg(&bias[r * OUT_DIM + 2 * lane]);
        t1 += __ldg(&bias[r * OUT_DIM + 2 * lane + 1]);
    }
    t0 *= (1.f / 3.f);
    t1 *= (1.f / 3.f);
    if (LAYER == 1) {
        float sq = t0 * t0 + t1 * t1;
#pragma unroll
        for (int o = 16; o > 0; o >>= 1) sq += __shfl_xor_sync(0xffffffffu, sq, o);
        float inv = 1.f / fmaxf(sqrtf(sq), 1e-12f);
        t0 = fmaxf(t0 * inv, 0.f);
        t1 = fmaxf(t1 * inv, 0.f);
        ((__half2*)outp)[(size_t)d * (OUT_DIM / 2) + lane] =
            __float22half2_rn(make_float2(t0, t1));
    } else {
        ((float2*)outp)[(size_t)d * (OUT_DIM / 2) + lane] = make_float2(t0, t1);
    }
}

// ---------------- launch -----------------------------------------------------
extern "C" void kernel_launch(void* const* d_in, const int* in_sizes, int n_in,
                              void* d_out, int out_size) {
    const float* x      = (const float*)d_in[0];
    const int*   ei0    = (const int*)d_in[1];
    const int*   ei1    = (const int*)d_in[2];
    const int*   ei2    = (const int*)d_in[3];
    const float* W1     = (const float*)d_in[4];
    const float* asrc1  = (const float*)d_in[5];
    const float* adst1  = (const float*)d_in[6];
    const float* b1     = (const float*)d_in[7];
    const float* W2     = (const float*)d_in[8];
    const float* asrc2  = (const float*)d_in[9];
    const float* adst2  = (const float*)d_in[10];
    const float* b2     = (const float*)d_in[11];

    __half* xh;   cudaGetSymbolAddress((void**)&xh, g_xh);
    __half* hmid; cudaGetSymbolAddress((void**)&hmid, g_hmid);

    // g_cnt / g_lookback zero on entry (BSS first run; agg2 tail thereafter)
    k_hist_convert<<<HB + CB, 256>>>(ei0, ei1, ei2, (const float4*)x);   // 1
    k_scan_lookback<<<NB_SCAN, 256>>>();                                  // 2
    k_scatter<<<HB, 256>>>(ei0, ei1, ei2);                                // 3

    dim3 ggrid(GB, 1, RR);
    k_gemm_tc<IN_DIM><<<ggrid, 256>>>(xh, W1, asrc1, adst1);             // 4 (captured)
    k_weight<<<HB, 256>>>();                                              // 5
    k_agg<1><<<(NN * 32 + 255) / 256, 256>>>(b1, hmid);                  // 6

    k_gemm_tc<OUT_DIM><<<ggrid, 256>>>(hmid, W2, asrc2, adst2);          // 7
    k_weight<<<HB, 256>>>();                                              // 8
    k_agg<2><<<(NN * 32 + 255) / 256, 256>>>(b2, d_out);                 // 9
}